// round 2
// baseline (speedup 1.0000x reference)
#include <cuda_runtime.h>

#define B_ 2
#define F_ 128
#define N_ 192
#define S_ 192
#define H_ 4
#define D_ 64
#define HD_ 256
#define GG 6            // i's per attn block
#define CJ 32           // j-chunk
#define NCHUNK (N_/CJ)  // 6
#define LOG2E 1.4426950408889634f

// exp tables: EUP[bh][i][s] = (exp2(u), exp2(0.2u)) masked; EVP[bh][s][j] = (exp2(v), exp2(0.2v))
static __device__ float2 d_EUP[B_*H_*N_*S_];
static __device__ float2 d_EVP[B_*H_*S_*N_];
static __device__ float d_P[F_*8];
static __device__ float d_Q[8];
static __device__ float d_colsum[B_*F_];
static __device__ float d_sumg[HD_];

__device__ __forceinline__ float ex2f(float x){ float r; asm("ex2.approx.ftz.f32 %0, %1;" : "=f"(r) : "f"(x)); return r; }
__device__ __forceinline__ float rcpf(float x){ float r; asm("rcp.approx.ftz.f32 %0, %1;" : "=f"(r) : "f"(x)); return r; }
__device__ __forceinline__ unsigned long long pk2(float x, float y){
    unsigned long long p; asm("mov.b64 %0, {%1,%2};" : "=l"(p) : "f"(x), "f"(y)); return p;
}
// max(u.x*v.x, u.y*v.y) via packed f32x2 multiply
__device__ __forceinline__ float pmax(unsigned long long up, float vx, float vy){
    unsigned long long vp, r;
    asm("mov.b64 %0, {%1,%2};" : "=l"(vp) : "f"(vx), "f"(vy));
    asm("mul.rn.f32x2 %0, %1, %2;" : "=l"(r) : "l"(up), "l"(vp));
    float lo, hi;
    asm("mov.b64 {%0,%1}, %2;" : "=f"(lo), "=f"(hi) : "l"(r));
    return fmaxf(lo, hi);
}

// Fold W_attn into W_lin/b_lin; pre-scale by log2(e); fold b_attn into src bias.
__global__ void k_prep(const float* __restrict__ Wl, const float* __restrict__ bl,
                       const float* __restrict__ Wa, const float* __restrict__ ba){
    int t = threadIdx.x;
    if (t < 512){
        int f = t >> 2, h = t & 3;
        float ps = 0.f, pd = 0.f;
        #pragma unroll 8
        for (int d = 0; d < D_; ++d){
            float wl = Wl[f*HD_ + h*D_ + d];
            ps += wl * Wa[d];
            pd += wl * Wa[D_ + d];
        }
        d_P[f*8 + h]     = ps * LOG2E;
        d_P[f*8 + 4 + h] = pd * LOG2E;
    }
    if (t < 8){
        int which = t >> 2, h = t & 3;
        float q = 0.f;
        for (int d = 0; d < D_; ++d) q += bl[h*D_ + d] * Wa[which*D_ + d];
        if (which == 0) q += ba[0];
        d_Q[which*4 + h] = q * LOG2E;
    }
}

__global__ void k_colsum(const float* __restrict__ X){
    int bf = blockIdx.x;
    const float4* p = (const float4*)(X + (size_t)bf * (N_*S_));
    float acc = 0.f;
    #pragma unroll 4
    for (int i = threadIdx.x; i < (N_*S_)/4; i += 256){
        float4 v = p[i];
        acc += (v.x + v.y) + (v.z + v.w);
    }
    __shared__ float sh[256];
    sh[threadIdx.x] = acc; __syncthreads();
    for (int o = 128; o > 0; o >>= 1){
        if (threadIdx.x < o) sh[threadIdx.x] += sh[threadIdx.x + o];
        __syncthreads();
    }
    if (threadIdx.x == 0) d_colsum[bf] = sh[0];
}

__global__ void k_sumg(const float* __restrict__ Wl, const float* __restrict__ bl){
    int c = threadIdx.x;
    float acc = (float)(B_*N_*S_) * bl[c];
    for (int f = 0; f < F_; ++f)
        acc += (d_colsum[f] + d_colsum[F_ + f]) * Wl[f*HD_ + c];
    d_sumg[c] = acc;
}

// Projection (128->8 GEMV per (b,n,s)) + exp-table epilogue. MLP-16 load batching.
__global__ void __launch_bounds__(192) k_proj(const float* __restrict__ X,
                                              const int* __restrict__ A){
    __shared__ float sP[F_*8];
    __shared__ float sQ[8];
    int b = blockIdx.x / N_, n = blockIdx.x % N_;
    int t = threadIdx.x;
    for (int i = t; i < F_*8; i += 192) sP[i] = d_P[i];
    if (t < 8) sQ[t] = d_Q[t];
    __syncthreads();
    float acc[8];
    #pragma unroll
    for (int k = 0; k < 8; ++k) acc[k] = 0.f;
    const float* xp = X + ((size_t)(b*F_)*N_ + n)*S_ + t;
    #pragma unroll
    for (int f0 = 0; f0 < F_; f0 += 16){
        float xv[16];
        #pragma unroll
        for (int k = 0; k < 16; ++k) xv[k] = xp[(size_t)(f0+k) * (N_*S_)];
        #pragma unroll
        for (int k = 0; k < 16; ++k){
            float4 p0 = ((const float4*)sP)[(f0+k)*2];
            float4 p1 = ((const float4*)sP)[(f0+k)*2 + 1];
            acc[0] += xv[k]*p0.x; acc[1] += xv[k]*p0.y; acc[2] += xv[k]*p0.z; acc[3] += xv[k]*p0.w;
            acc[4] += xv[k]*p1.x; acc[5] += xv[k]*p1.y; acc[6] += xv[k]*p1.z; acc[7] += xv[k]*p1.w;
        }
    }
    int av = A[t*N_ + n];   // mask A[s=t, i=n]
    #pragma unroll
    for (int h = 0; h < H_; ++h){
        int bh = b*H_ + h;
        float u = acc[h] + sQ[h];
        float2 eu = av ? make_float2(ex2f(u), ex2f(0.2f*u)) : make_float2(0.f, 0.f);
        d_EUP[((size_t)bh*N_ + n)*S_ + t] = eu;
        float v = acc[4+h] + sQ[4+h];
        d_EVP[((size_t)bh*S_ + t)*N_ + n] = make_float2(ex2f(v), ex2f(0.2f*v));
    }
}

// smem layout (bytes)
#define SM_VT   0                       // float2 [192][36]  = 55296
#define SM_E    55296                   // float  [192][36]  = 27648
#define SM_SU   82944                   // float2 [GG][192]  = 9216
#define SM_ZP   92160                   // float  [256]      = 1024
#define SM_IZ   93184                   // float  [32]       = 128
#define SM_SG   93312                   // float  [64]       = 256
#define SM_BYTES 93568

__global__ void __launch_bounds__(256) k_attn(float* __restrict__ out){
    extern __shared__ char smraw[];
    float2* VTs = (float2*)(smraw + SM_VT);
    float*  Es  = (float*) (smraw + SM_E);
    float2* SUs = (float2*)(smraw + SM_SU);
    float*  Zp2 = (float*) (smraw + SM_ZP);
    float*  iZ  = (float*) (smraw + SM_IZ);
    float*  sgd = (float*) (smraw + SM_SG);

    int i0 = blockIdx.x * GG;
    int h  = blockIdx.y, b = blockIdx.z;
    int bh = b*H_ + h;
    int t  = threadIdx.x;

    for (int idx = t; idx < GG*S_; idx += 256){
        int ii = idx / S_, s = idx % S_;
        SUs[idx] = d_EUP[((size_t)bh*N_ + i0 + ii)*S_ + s];
    }
    if (t < D_) sgd[t] = d_sumg[h*D_ + t];

    float areg[GG];
    #pragma unroll
    for (int i = 0; i < GG; ++i) areg[i] = 0.f;

    int jq = t & 7;     // 8 groups of 4 j
    int sg = t >> 3;    // 32 groups of 6 s
    int lane = t & 31, w = t >> 5;

    for (int jc = 0; jc < NCHUNK; ++jc){
        int j0 = jc * CJ;
        for (int idx = t; idx < S_*CJ; idx += 256){
            int s = idx >> 5, jl = idx & 31;
            VTs[s*36 + jl] = d_EVP[((size_t)bh*S_ + s)*N_ + j0 + jl];
        }
        __syncthreads();

        for (int i = 0; i < GG; ++i){
            float z0=0.f, z1=0.f, z2=0.f, z3=0.f;
            #pragma unroll
            for (int k = 0; k < 6; ++k){
                int s = sg*6 + k;
                float2 u2 = SUs[i*S_ + s];
                unsigned long long up = pk2(u2.x, u2.y);
                const float4* vp = (const float4*)(VTs + s*36 + jq*4);
                float4 va = vp[0];
                float4 vb = vp[1];
                float e0 = pmax(up, va.x, va.y);
                float e1 = pmax(up, va.z, va.w);
                float e2 = pmax(up, vb.x, vb.y);
                float e3 = pmax(up, vb.z, vb.w);
                *(float4*)(Es + s*36 + jq*4) = make_float4(e0, e1, e2, e3);
                z0 += e0; z1 += e1; z2 += e2; z3 += e3;
            }
            // warp-level reduce across the 4 sg rows of this warp
            unsigned m = 0xFFFFFFFFu;
            z0 += __shfl_down_sync(m, z0, 16); z0 += __shfl_down_sync(m, z0, 8);
            z1 += __shfl_down_sync(m, z1, 16); z1 += __shfl_down_sync(m, z1, 8);
            z2 += __shfl_down_sync(m, z2, 16); z2 += __shfl_down_sync(m, z2, 8);
            z3 += __shfl_down_sync(m, z3, 16); z3 += __shfl_down_sync(m, z3, 8);
            if (lane < 8){
                Zp2[w*32 + lane*4 + 0] = z0;
                Zp2[w*32 + lane*4 + 1] = z1;
                Zp2[w*32 + lane*4 + 2] = z2;
                Zp2[w*32 + lane*4 + 3] = z3;
            }
            __syncthreads();
            if (t < 32){
                float z = 0.f;
                #pragma unroll
                for (int ww = 0; ww < 8; ++ww) z += Zp2[ww*32 + t];
                iZ[t] = (z > 0.f) ? rcpf(z) : 0.f;
            }
            __syncthreads();
            if (t < S_){
                float part = 0.f;
                const float4* Er = (const float4*)(Es + t*36);
                const float4* zr = (const float4*)iZ;
                #pragma unroll
                for (int q = 0; q < 8; ++q){
                    float4 e4 = Er[q];
                    float4 z4 = zr[q];
                    part += e4.x*z4.x + e4.y*z4.y + e4.z*z4.z + e4.w*z4.w;
                }
                areg[i] += part;
            }
            __syncthreads();
        }
    }

    // write alpha to smem (alias VT), then vectorized output
    float* AL = (float*)(smraw + SM_VT);
    if (t < S_){
        #pragma unroll
        for (int i = 0; i < GG; ++i) AL[i*S_ + t] = areg[i];
    }
    __syncthreads();
    for (int idx = t; idx < GG*D_*(S_/4); idx += 256){
        int i  = idx / (D_*(S_/4));
        int r  = idx % (D_*(S_/4));
        int d  = r / (S_/4);
        int s4 = r % (S_/4);
        float4 a4 = *(const float4*)(AL + i*S_ + s4*4);
        float sv = sgd[d];
        float4 o = make_float4(a4.x*sv, a4.y*sv, a4.z*sv, a4.w*sv);
        *(float4*)(out + ((size_t)(b*HD_ + h*D_ + d)*N_ + i0 + i)*S_ + s4*4) = o;
    }
}

extern "C" void kernel_launch(void* const* d_in, const int* in_sizes, int n_in,
                              void* d_out, int out_size){
    const float* X  = (const float*)d_in[0];
    const int*   A  = (const int*)  d_in[1];
    const float* Wl = (const float*)d_in[2];
    const float* bl = (const float*)d_in[3];
    const float* Wa = (const float*)d_in[4];
    const float* ba = (const float*)d_in[5];
    float* out = (float*)d_out;

    cudaFuncSetAttribute(k_attn, cudaFuncAttributeMaxDynamicSharedMemorySize, SM_BYTES);

    k_prep  <<<1, 512>>>(Wl, bl, Wa, ba);
    k_colsum<<<B_*F_, 256>>>(X);
    k_sumg  <<<1, HD_>>>(Wl, bl);
    k_proj  <<<B_*N_, 192>>>(X, A);
    dim3 g(N_/GG, H_, B_);
    k_attn  <<<g, 256, SM_BYTES>>>(out);
}

// round 4
// speedup vs baseline: 1.4731x; 1.4731x over previous
#include <cuda_runtime.h>

#define B_ 2
#define F_ 128
#define N_ 192
#define S_ 192
#define H_ 4
#define D_ 64
#define HD_ 256
#define CJ 32
#define NCH (N_/CJ)     // 6
#define EPITCH 36
#define LOG2E 1.4426950408889634f

// SS[bh][i][s] = log2e*(s_src + q_src + b_attn), masked to -1e30 where A[s,i]==0
// SD[bh][s][j] = log2e*(s_dst + q_dst)
static __device__ float d_SS[B_*H_*N_*S_];
static __device__ float d_SD[B_*H_*S_*N_];
static __device__ float d_P[F_*8];
static __device__ float d_Q[8];
static __device__ float d_colsum[B_*F_];
static __device__ float d_sumg[HD_];

__device__ __forceinline__ float ex2f(float x){ float r; asm("ex2.approx.ftz.f32 %0, %1;" : "=f"(r) : "f"(x)); return r; }
__device__ __forceinline__ float rcpf(float x){ float r; asm("rcp.approx.ftz.f32 %0, %1;" : "=f"(r) : "f"(x)); return r; }

// ---- launch 1: fold W_attn into W_lin/b_lin (tiny) ----
__global__ void k_prep(const float* __restrict__ Wl, const float* __restrict__ bl,
                       const float* __restrict__ Wa, const float* __restrict__ ba){
    int t = threadIdx.x;
    if (t < 512){
        int f = t >> 2, h = t & 3;
        float ps = 0.f, pd = 0.f;
        #pragma unroll 8
        for (int d = 0; d < D_; ++d){
            float wl = Wl[f*HD_ + h*D_ + d];
            ps += wl * Wa[d];
            pd += wl * Wa[D_ + d];
        }
        d_P[f*8 + h]     = ps * LOG2E;
        d_P[f*8 + 4 + h] = pd * LOG2E;
    }
    if (t < 8){
        int which = t >> 2, h = t & 3;
        float q = 0.f;
        for (int d = 0; d < D_; ++d) q += bl[h*D_ + d] * Wa[which*D_ + d];
        if (which == 0) q += ba[0];
        d_Q[which*4 + h] = q * LOG2E;
    }
}

// ---- launch 2: proj (blocks 0..383) + colsum (blocks 384..639), concurrent ----
__global__ void __launch_bounds__(192) k_main(const float* __restrict__ X,
                                              const int* __restrict__ A){
    int t = threadIdx.x;
    if (blockIdx.x >= 384){
        // colsum over (n,s) for bf = blockIdx.x-384
        int bf = blockIdx.x - 384;
        const float4* p = (const float4*)(X + (size_t)bf * (N_*S_));
        float acc = 0.f;
        #pragma unroll 4
        for (int i = t; i < (N_*S_)/4; i += 192){
            float4 v = p[i];
            acc += (v.x + v.y) + (v.z + v.w);
        }
        // warp-shuffle reduce (correct for 192 = 6 warps)
        unsigned m = 0xFFFFFFFFu;
        acc += __shfl_down_sync(m, acc, 16);
        acc += __shfl_down_sync(m, acc, 8);
        acc += __shfl_down_sync(m, acc, 4);
        acc += __shfl_down_sync(m, acc, 2);
        acc += __shfl_down_sync(m, acc, 1);
        __shared__ float wp[6];
        if ((t & 31) == 0) wp[t >> 5] = acc;
        __syncthreads();
        if (t == 0)
            d_colsum[bf] = ((wp[0]+wp[1]) + (wp[2]+wp[3])) + (wp[4]+wp[5]);
        return;
    }
    // projection: 128->8 GEMV per (b,n,s=t), MLP-16 batches
    __shared__ float sP[F_*8];
    __shared__ float sQ[8];
    int b = blockIdx.x / N_, n = blockIdx.x % N_;
    for (int i = t; i < F_*8; i += 192) sP[i] = d_P[i];
    if (t < 8) sQ[t] = d_Q[t];
    __syncthreads();
    float acc[8];
    #pragma unroll
    for (int k = 0; k < 8; ++k) acc[k] = 0.f;
    const float* xp = X + ((size_t)(b*F_)*N_ + n)*S_ + t;
    #pragma unroll
    for (int f0 = 0; f0 < F_; f0 += 16){
        float xv[16];
        #pragma unroll
        for (int k = 0; k < 16; ++k) xv[k] = xp[(size_t)(f0+k) * (N_*S_)];
        #pragma unroll
        for (int k = 0; k < 16; ++k){
            float4 p0 = ((const float4*)sP)[(f0+k)*2];
            float4 p1 = ((const float4*)sP)[(f0+k)*2 + 1];
            acc[0] += xv[k]*p0.x; acc[1] += xv[k]*p0.y; acc[2] += xv[k]*p0.z; acc[3] += xv[k]*p0.w;
            acc[4] += xv[k]*p1.x; acc[5] += xv[k]*p1.y; acc[6] += xv[k]*p1.z; acc[7] += xv[k]*p1.w;
        }
    }
    int av = A[t*N_ + n];   // mask A[s=t, i=n]
    #pragma unroll
    for (int h = 0; h < H_; ++h){
        int bh = b*H_ + h;
        float u = acc[h] + sQ[h];
        d_SS[((size_t)bh*N_ + n)*S_ + t] = av ? u : -1e30f;
        d_SD[((size_t)bh*S_ + t)*N_ + n] = acc[4+h] + sQ[4+h];
    }
}

// ---- launch 3: sum_g[c] = colsumX · W_lin[:,c] + R*b_lin[c] ----
__global__ void __launch_bounds__(256) k_sumg(const float* __restrict__ Wl,
                                              const float* __restrict__ bl){
    __shared__ float cs[F_];
    int t = threadIdx.x;
    if (t < F_) cs[t] = d_colsum[t] + d_colsum[F_ + t];
    __syncthreads();
    float acc = (float)(B_*N_*S_) * bl[t];
    #pragma unroll
    for (int f0 = 0; f0 < F_; f0 += 16){
        float wv[16];
        #pragma unroll
        for (int k = 0; k < 16; ++k) wv[k] = Wl[(f0+k)*HD_ + t];
        #pragma unroll
        for (int k = 0; k < 16; ++k) acc += cs[f0+k] * wv[k];
    }
    d_sumg[t] = acc;
}

// ---- launch 4: attention tile, one CTA per (b,h,i) ----
__global__ void __launch_bounds__(192) k_attn(float* __restrict__ out){
    __shared__ float w[S_];
    __shared__ float E[S_][EPITCH];     // row = s, 144B rows (16B aligned, conflict-free)
    __shared__ float Zp[6][CJ];
    __shared__ float iZ[CJ];
    __shared__ float sg[D_];
    __shared__ float AL[S_];

    int i = blockIdx.x, h = blockIdx.y, b = blockIdx.z;
    int bh = b*H_ + h;
    int t  = threadIdx.x;

    w[t] = d_SS[((size_t)bh*N_ + i)*S_ + t];   // mask+bias already folded
    if (t < D_) sg[t] = d_sumg[h*D_ + t];
    __syncthreads();

    const float* V = d_SD + (size_t)bh*S_*N_;
    int jl  = t & 31;          // warp-aligned: warp = one s-group
    int sgp = t >> 5;
    float alpha = 0.f;

    for (int jc = 0; jc < NCH; ++jc){
        int j = jc*CJ + jl;
        float z = 0.f;
        #pragma unroll 8
        for (int k = 0; k < 32; ++k){
            int s = sgp*32 + k;
            float a = w[s] + __ldg(&V[s*N_ + j]);     // w[s] broadcast within warp
            float e = ex2f(fmaxf(a, 0.2f*a));
            E[s][jl] = e;                             // consecutive banks, no conflict
            z += e;
        }
        Zp[sgp][jl] = z;
        __syncthreads();
        if (t < CJ){
            float Z = Zp[0][t]+Zp[1][t]+Zp[2][t]+Zp[3][t]+Zp[4][t]+Zp[5][t];
            iZ[t] = (Z > 0.f) ? rcpf(Z) : 0.f;        // all-masked column -> 0 (NaN->0)
        }
        __syncthreads();
        {
            const float4* Er = (const float4*)&E[t][0];
            const float4* zr = (const float4*)iZ;
            float part = 0.f;
            #pragma unroll
            for (int q = 0; q < 8; ++q){
                float4 e4 = Er[q];
                float4 z4 = zr[q];
                part += e4.x*z4.x + e4.y*z4.y + e4.z*z4.z + e4.w*z4.w;
            }
            alpha += part;
        }
        __syncthreads();
    }

    AL[t] = alpha;
    __syncthreads();
    // output: alpha[s] * sum_g[d], vectorized float4 along s
    for (int idx = t; idx < D_*(S_/4); idx += 192){
        int d  = idx / (S_/4);
        int s4 = idx % (S_/4);
        float4 a4 = *(const float4*)(AL + s4*4);
        float sv = sg[d];
        float4 o = make_float4(a4.x*sv, a4.y*sv, a4.z*sv, a4.w*sv);
        *(float4*)(out + ((size_t)(b*HD_ + h*D_ + d)*N_ + i)*S_ + s4*4) = o;
    }
}

extern "C" void kernel_launch(void* const* d_in, const int* in_sizes, int n_in,
                              void* d_out, int out_size){
    const float* X  = (const float*)d_in[0];
    const int*   A  = (const int*)  d_in[1];
    const float* Wl = (const float*)d_in[2];
    const float* bl = (const float*)d_in[3];
    const float* Wa = (const float*)d_in[4];
    const float* ba = (const float*)d_in[5];
    float* out = (float*)d_out;

    k_prep <<<1, 512>>>(Wl, bl, Wa, ba);
    k_main <<<640, 192>>>(X, A);
    k_sumg <<<1, HD_>>>(Wl, bl);
    dim3 g(N_, H_, B_);
    k_attn <<<g, 192>>>(out);
}

// round 5
// speedup vs baseline: 1.8420x; 1.2504x over previous
#include <cuda_runtime.h>

#define B_ 2
#define F_ 128
#define N_ 192
#define S_ 192
#define H_ 4
#define D_ 64
#define HD_ 256
#define LOG2E 1.4426950408889634f

// SS[bh][i][s] = log2e*(s_src + q_src + b_attn), masked to -1e30 where A[s,i]==0
// SDT[bh][j][s] = log2e*(s_dst + q_dst)   (TRANSPOSED: j-major for coalesced col reads)
static __device__ float d_SS [B_*H_*N_*S_];
static __device__ float d_SDT[B_*H_*N_*S_];
static __device__ float d_P[F_*8];
static __device__ float d_Q[8];
static __device__ float d_colsum[B_*F_];
static __device__ float d_sumg[HD_];

__device__ __forceinline__ float ex2f(float x){ float r; asm("ex2.approx.ftz.f32 %0, %1;" : "=f"(r) : "f"(x)); return r; }
__device__ __forceinline__ float rcpf(float x){ float r; asm("rcp.approx.ftz.f32 %0, %1;" : "=f"(r) : "f"(x)); return r; }

// ---- launch 1: fold W_attn into W_lin/b_lin (tiny) ----
__global__ void k_prep(const float* __restrict__ Wl, const float* __restrict__ bl,
                       const float* __restrict__ Wa, const float* __restrict__ ba){
    int t = threadIdx.x;
    if (t < 512){
        int f = t >> 2, h = t & 3;
        float ps = 0.f, pd = 0.f;
        #pragma unroll 8
        for (int d = 0; d < D_; ++d){
            float wl = Wl[f*HD_ + h*D_ + d];
            ps += wl * Wa[d];
            pd += wl * Wa[D_ + d];
        }
        d_P[f*8 + h]     = ps * LOG2E;
        d_P[f*8 + 4 + h] = pd * LOG2E;
    }
    if (t < 8){
        int which = t >> 2, h = t & 3;
        float q = 0.f;
        for (int d = 0; d < D_; ++d) q += bl[h*D_ + d] * Wa[which*D_ + d];
        if (which == 0) q += ba[0];
        d_Q[which*4 + h] = q * LOG2E;
    }
}

// ---- launch 2: proj (blocks 0..127, 3 n's each) + colsum (blocks 128..383) ----
__global__ void __launch_bounds__(576) k_main(const float* __restrict__ X,
                                              const int* __restrict__ A){
    int t = threadIdx.x;
    if (blockIdx.x >= 128){
        int bf = blockIdx.x - 128;
        const float4* p = (const float4*)(X + (size_t)bf * (N_*S_));
        float acc = 0.f;
        #pragma unroll 4
        for (int i = t; i < (N_*S_)/4; i += 576){
            float4 v = p[i];
            acc += (v.x + v.y) + (v.z + v.w);
        }
        unsigned m = 0xFFFFFFFFu;
        acc += __shfl_down_sync(m, acc, 16);
        acc += __shfl_down_sync(m, acc, 8);
        acc += __shfl_down_sync(m, acc, 4);
        acc += __shfl_down_sync(m, acc, 2);
        acc += __shfl_down_sync(m, acc, 1);
        __shared__ float wparts[18];
        if ((t & 31) == 0) wparts[t >> 5] = acc;
        __syncthreads();
        if (t == 0){
            float s = 0.f;
            #pragma unroll
            for (int k = 0; k < 18; ++k) s += wparts[k];
            d_colsum[bf] = s;
        }
        return;
    }
    // projection: 128->8 GEMV; block = (b, n0..n0+2), thread = (n_local, s)
    __shared__ float sP[F_*8];
    __shared__ float sQ[8];
    int b  = blockIdx.x >> 6;
    int n0 = (blockIdx.x & 63) * 3;
    int n  = n0 + t / 192;
    int s  = t % 192;
    for (int i = t; i < F_*8; i += 576) sP[i] = d_P[i];
    if (t < 8) sQ[t] = d_Q[t];
    __syncthreads();
    float acc[8];
    #pragma unroll
    for (int k = 0; k < 8; ++k) acc[k] = 0.f;
    const float* xp = X + ((size_t)(b*F_)*N_ + n)*S_ + s;
    #pragma unroll
    for (int f0 = 0; f0 < F_; f0 += 16){
        float xv[16];
        #pragma unroll
        for (int k = 0; k < 16; ++k) xv[k] = xp[(size_t)(f0+k) * (N_*S_)];
        #pragma unroll
        for (int k = 0; k < 16; ++k){
            float4 p0 = ((const float4*)sP)[(f0+k)*2];
            float4 p1 = ((const float4*)sP)[(f0+k)*2 + 1];
            acc[0] += xv[k]*p0.x; acc[1] += xv[k]*p0.y; acc[2] += xv[k]*p0.z; acc[3] += xv[k]*p0.w;
            acc[4] += xv[k]*p1.x; acc[5] += xv[k]*p1.y; acc[6] += xv[k]*p1.z; acc[7] += xv[k]*p1.w;
        }
    }
    int av = A[s*N_ + n];   // mask A[s, i=n]
    #pragma unroll
    for (int h = 0; h < H_; ++h){
        int bh = b*H_ + h;
        float u = acc[h] + sQ[h];
        d_SS [((size_t)bh*N_ + n)*S_ + s] = av ? u : -1e30f;
        d_SDT[((size_t)bh*N_ + n)*S_ + s] = acc[4+h] + sQ[4+h];   // [bh][j=n][s], coalesced
    }
}

// ---- launch 3: sum_g[c] = colsumX · W_lin[:,c] + R*b_lin[c] ----
__global__ void __launch_bounds__(256) k_sumg(const float* __restrict__ Wl,
                                              const float* __restrict__ bl){
    __shared__ float cs[F_];
    int t = threadIdx.x;
    if (t < F_) cs[t] = d_colsum[t] + d_colsum[F_ + t];
    __syncthreads();
    float acc = (float)(B_*N_*S_) * bl[t];
    #pragma unroll
    for (int f0 = 0; f0 < F_; f0 += 16){
        float wv[16];
        #pragma unroll
        for (int k = 0; k < 16; ++k) wv[k] = Wl[(f0+k)*HD_ + t];
        #pragma unroll
        for (int k = 0; k < 16; ++k) acc += cs[f0+k] * wv[k];
    }
    d_sumg[t] = acc;
}

// ---- launch 4: attention, one CTA per (b,h,i); warp owns 32 columns j ----
// lane s-mapping: positions {4l,4l+1,4l+2,4l+3} (k=0..3) and {128+2l, 128+2l+1} (k=4,5)
__global__ void __launch_bounds__(192) k_attn(float* __restrict__ out){
    __shared__ float w[S_];
    __shared__ float AL[6][S_];
    __shared__ float ALf[S_];
    __shared__ float sg[D_];

    int i = blockIdx.x, h = blockIdx.y, b = blockIdx.z;
    int bh = b*H_ + h;
    int t  = threadIdx.x, lane = t & 31, wp = t >> 5;

    w[t] = d_SS[((size_t)bh*N_ + i)*S_ + t];   // mask+bias already folded
    if (t < D_) sg[t] = d_sumg[h*D_ + t];
    __syncthreads();

    float wr[6], acc[6];
    {
        float4 w4 = *(const float4*)(w + 4*lane);
        float2 w2 = *(const float2*)(w + 128 + 2*lane);
        wr[0]=w4.x; wr[1]=w4.y; wr[2]=w4.z; wr[3]=w4.w; wr[4]=w2.x; wr[5]=w2.y;
    }
    #pragma unroll
    for (int k = 0; k < 6; ++k) acc[k] = 0.f;

    const float* VT = d_SDT + (size_t)bh*N_*S_;
    const unsigned m = 0xFFFFFFFFu;

    #pragma unroll 2
    for (int jj = 0; jj < 32; ++jj){
        const float* vrow = VT + (size_t)(wp*32 + jj)*S_;
        float4 v4 = __ldg((const float4*)(vrow + 4*lane));
        float2 v2 = __ldg((const float2*)(vrow + 128 + 2*lane));
        float e[6];
        float a;
        a = wr[0]+v4.x; e[0] = ex2f(fmaxf(a, 0.2f*a));
        a = wr[1]+v4.y; e[1] = ex2f(fmaxf(a, 0.2f*a));
        a = wr[2]+v4.z; e[2] = ex2f(fmaxf(a, 0.2f*a));
        a = wr[3]+v4.w; e[3] = ex2f(fmaxf(a, 0.2f*a));
        a = wr[4]+v2.x; e[4] = ex2f(fmaxf(a, 0.2f*a));
        a = wr[5]+v2.y; e[5] = ex2f(fmaxf(a, 0.2f*a));
        float z = ((e[0]+e[1]) + (e[2]+e[3])) + (e[4]+e[5]);
        z += __shfl_xor_sync(m, z, 16);
        z += __shfl_xor_sync(m, z, 8);
        z += __shfl_xor_sync(m, z, 4);
        z += __shfl_xor_sync(m, z, 2);
        z += __shfl_xor_sync(m, z, 1);
        float iz = (z > 0.f) ? rcpf(z) : 0.f;   // all-masked column -> 0 (NaN->0)
        #pragma unroll
        for (int k = 0; k < 6; ++k) acc[k] += e[k]*iz;
    }

    // stash per-warp alpha partials
    AL[wp][4*lane+0] = acc[0];
    AL[wp][4*lane+1] = acc[1];
    AL[wp][4*lane+2] = acc[2];
    AL[wp][4*lane+3] = acc[3];
    AL[wp][128+2*lane+0] = acc[4];
    AL[wp][128+2*lane+1] = acc[5];
    __syncthreads();
    {
        float s = ((AL[0][t]+AL[1][t]) + (AL[2][t]+AL[3][t])) + (AL[4][t]+AL[5][t]);
        ALf[t] = s;
    }
    __syncthreads();

    // output: alpha[s] * sum_g[d], float4 along s
    for (int idx = t; idx < D_*(S_/4); idx += 192){
        int d  = idx / (S_/4);
        int s4 = idx % (S_/4);
        float4 a4 = *(const float4*)(ALf + s4*4);
        float sv = sg[d];
        float4 o = make_float4(a4.x*sv, a4.y*sv, a4.z*sv, a4.w*sv);
        *(float4*)(out + ((size_t)(b*HD_ + h*D_ + d)*N_ + i)*S_ + s4*4) = o;
    }
}

extern "C" void kernel_launch(void* const* d_in, const int* in_sizes, int n_in,
                              void* d_out, int out_size){
    const float* X  = (const float*)d_in[0];
    const int*   A  = (const int*)  d_in[1];
    const float* Wl = (const float*)d_in[2];
    const float* bl = (const float*)d_in[3];
    const float* Wa = (const float*)d_in[4];
    const float* ba = (const float*)d_in[5];
    float* out = (float*)d_out;

    k_prep <<<1, 512>>>(Wl, bl, Wa, ba);
    k_main <<<384, 576>>>(X, A);
    k_sumg <<<1, HD_>>>(Wl, bl);
    dim3 g(N_, H_, B_);
    k_attn <<<g, 192>>>(out);
}